// round 5
// baseline (speedup 1.0000x reference)
#include <cuda_runtime.h>
#include <cuda_bf16.h>
#include <math.h>
#include <stdint.h>

#define N_USERS 100000
#define N_ITEMS 50000
#define N_TOT   150000
#define IN_DIM  768
#define BR      64
#define NE      2097152
#define BATCHB  4096
#define NCAND   128
#define NNEG    16
#define DIM     128
#define INV_SQRT2 0.70710678118f
#define NB_SCAN 147

// ---------------- scratch (device globals; NEVER referenced from host code) ----------------
__device__ float g_ego_a[(size_t)N_TOT * BR];
__device__ float g_ego_b[(size_t)N_TOT * BR];
__device__ float g_acc  [(size_t)N_TOT * BR];
__device__ float g_i_all[(size_t)N_ITEMS * DIM];
__device__ float g_batch_u[(size_t)BATCHB * DIM];
__device__ int   g_row_ptr[N_TOT + 1];
__device__ int   g_row_cnt[N_TOT];
__device__ int   g_row_fill[N_TOT];
__device__ int2  g_cv[NE];
__device__ int   g_bsum[256];
__device__ float g_loss;

// ---------------- init / zero ----------------
__global__ void k_zero() {
    int i = blockIdx.x * blockDim.x + threadIdx.x;
    if (i < N_TOT) { g_row_cnt[i] = 0; g_row_fill[i] = 0; }
    if (i == 0) g_loss = 0.0f;
}

__global__ void k_init_ego(const float* __restrict__ uw, const float* __restrict__ iw) {
    int idx = blockIdx.x * blockDim.x + threadIdx.x;
    if (idx >= N_TOT * BR) return;
    int row = idx >> 6, c = idx & 63;
    float v = (row < N_USERS) ? uw[row * BR + c] : iw[(row - N_USERS) * BR + c];
    g_ego_a[idx] = v;
    g_acc[idx]   = v;
}

// ---------------- CSR build ----------------
__global__ void k_hist(const int* __restrict__ rows) {
    int i = blockIdx.x * blockDim.x + threadIdx.x;
    if (i < NE) atomicAdd(&g_row_cnt[rows[i]], 1);
}

__global__ void k_scan1() {
    __shared__ int red[256];
    int b = blockIdx.x, t = threadIdx.x;
    int base = b * 1024 + t * 4;
    int s = 0;
    #pragma unroll
    for (int q = 0; q < 4; q++) { int i = base + q; if (i < N_TOT) s += g_row_cnt[i]; }
    red[t] = s; __syncthreads();
    for (int off = 128; off > 0; off >>= 1) {
        if (t < off) red[t] += red[t + off];
        __syncthreads();
    }
    if (t == 0) g_bsum[b] = red[0];
}

__global__ void k_scan2() {
    if (threadIdx.x == 0 && blockIdx.x == 0) {
        int run = 0;
        for (int i = 0; i < NB_SCAN; i++) { int t = g_bsum[i]; g_bsum[i] = run; run += t; }
    }
}

__global__ void k_scan3() {
    __shared__ int tsum[256];
    int b = blockIdx.x, t = threadIdx.x;
    int base = b * 1024 + t * 4;
    int c0 = 0, c1 = 0, c2 = 0, c3 = 0;
    if (base + 0 < N_TOT) c0 = g_row_cnt[base + 0];
    if (base + 1 < N_TOT) c1 = g_row_cnt[base + 1];
    if (base + 2 < N_TOT) c2 = g_row_cnt[base + 2];
    if (base + 3 < N_TOT) c3 = g_row_cnt[base + 3];
    int p1 = c0, p2 = c0 + c1, p3 = c0 + c1 + c2, s = p3 + c3;
    tsum[t] = s; __syncthreads();
    for (int off = 1; off < 256; off <<= 1) {
        int v = (t >= off) ? tsum[t - off] : 0;
        __syncthreads();
        tsum[t] += v;
        __syncthreads();
    }
    int excl = tsum[t] - s + g_bsum[b];
    if (base + 0 < N_TOT) g_row_ptr[base + 0] = excl;
    if (base + 1 < N_TOT) g_row_ptr[base + 1] = excl + p1;
    if (base + 2 < N_TOT) g_row_ptr[base + 2] = excl + p2;
    if (base + 3 < N_TOT) g_row_ptr[base + 3] = excl + p3;
    if (b == 0 && t == 0) g_row_ptr[N_TOT] = NE;
}

__global__ void k_scatter(const int* __restrict__ rows, const int* __restrict__ cols,
                          const float* __restrict__ vals) {
    int i = blockIdx.x * blockDim.x + threadIdx.x;
    if (i >= NE) return;
    int r = rows[i];
    int ofs = atomicAdd(&g_row_fill[r], 1);
    g_cv[g_row_ptr[r] + ofs] = make_int2(cols[i], __float_as_int(vals[i]));
}

// ---------------- SpMM: warp per destination row ----------------
template<bool LAST>
__global__ void k_spmm(int phase) {
    const float* __restrict__ in = (phase & 1) ? g_ego_b : g_ego_a;
    float* __restrict__ outp     = (phase & 1) ? g_ego_a : g_ego_b;
    int w = (blockIdx.x * blockDim.x + threadIdx.x) >> 5;
    int lane = threadIdx.x & 31;
    if (w >= N_TOT) return;
    int s = g_row_ptr[w], e = g_row_ptr[w + 1];
    float a0 = 0.0f, a1 = 0.0f;
    for (int base = s; base < e; base += 32) {
        int idx = base + lane;
        int c = 0; float v = 0.0f;
        if (idx < e) { int2 cv = __ldg(&g_cv[idx]); c = cv.x; v = __int_as_float(cv.y); }
        int cnt = min(32, e - base);
        for (int j = 0; j < cnt; j++) {
            int cc = __shfl_sync(0xffffffffu, c, j);
            float vv = __shfl_sync(0xffffffffu, v, j);
            float2 p = __ldg((const float2*)(in + (size_t)cc * BR) + lane);
            a0 = fmaf(vv, p.x, a0);
            a1 = fmaf(vv, p.y, a1);
        }
    }
    size_t o = (size_t)w * BR + 2 * lane;
    if (!LAST) {
        outp[o] = a0; outp[o + 1] = a1;
        g_acc[o] += a0; g_acc[o + 1] += a1;
    } else {
        float t0 = g_acc[o] + a0, t1 = g_acc[o + 1] + a1;
        if (w < N_USERS) {
            g_acc[o] = t0; g_acc[o + 1] = t1;   // users gathered later by k_collab_users
        } else {
            float ss = t0 * t0 + t1 * t1;
            #pragma unroll
            for (int off = 16; off > 0; off >>= 1) ss += __shfl_xor_sync(0xffffffffu, ss, off);
            float sc = INV_SQRT2 / fmaxf(sqrtf(ss), 1e-12f);
            size_t oi = (size_t)(w - N_USERS) * DIM + 2 * lane;
            g_i_all[oi] = t0 * sc; g_i_all[oi + 1] = t1 * sc;
        }
    }
}

__global__ void k_collab_users(const int* __restrict__ uids) {
    int w = (blockIdx.x * blockDim.x + threadIdx.x) >> 5;
    int lane = threadIdx.x & 31;
    if (w >= BATCHB) return;
    int u = uids[w];
    size_t o = (size_t)u * BR;
    float v0 = g_acc[o + lane], v1 = g_acc[o + lane + 32];
    float ss = v0 * v0 + v1 * v1;
    #pragma unroll
    for (int off = 16; off > 0; off >>= 1) ss += __shfl_xor_sync(0xffffffffu, ss, off);
    float sc = INV_SQRT2 / fmaxf(sqrtf(ss), 1e-12f);
    g_batch_u[(size_t)w * DIM + lane] = v0 * sc;
    g_batch_u[(size_t)w * DIM + lane + 32] = v1 * sc;
}

// ---------------- semantic GEMM (R2-proven fp32 SIMT version) ----------------
// out[row][64..127] = normalize(A[row]@W + b)/sqrt2. BM=128, BN=64, BK=16,
// 256 threads, thread tile 8x4, row-normalize in epilogue.
template<bool GATHER>
__global__ void k_sem_gemm(const float* __restrict__ A, const float* __restrict__ W,
                           const float* __restrict__ bias, const int* __restrict__ gidx,
                           int M) {
    float* __restrict__ outp = GATHER ? g_batch_u : g_i_all;
    __shared__ float As[16][128];
    __shared__ float Bs[16][64];
    __shared__ float Cs[128][68];

    int t = threadIdx.x;
    int rowbase = blockIdx.x * 128;
    int tx = t & 15, ty = t >> 4;

    float acc[8][4];
    #pragma unroll
    for (int i = 0; i < 8; i++)
        #pragma unroll
        for (int j = 0; j < 4; j++) acc[i][j] = 0.0f;

    int aRow0 = t >> 2;
    int aK4 = (t & 3) * 4;
    int gr0 = rowbase + aRow0;
    int gr1 = rowbase + aRow0 + 64;
    bool val0 = gr0 < M, val1 = gr1 < M;
    int srow0 = val0 ? (GATHER ? gidx[gr0] : gr0) : 0;
    int srow1 = val1 ? (GATHER ? gidx[gr1] : gr1) : 0;
    const float* rp0 = A + (size_t)srow0 * IN_DIM;
    const float* rp1 = A + (size_t)srow1 * IN_DIM;

    int bK = t >> 4;
    int bC = (t & 15) * 4;

    for (int k0 = 0; k0 < IN_DIM; k0 += 16) {
        float4 a0 = val0 ? *(const float4*)(rp0 + k0 + aK4) : make_float4(0, 0, 0, 0);
        float4 a1 = val1 ? *(const float4*)(rp1 + k0 + aK4) : make_float4(0, 0, 0, 0);
        float4 bv = *(const float4*)(W + (size_t)(k0 + bK) * BR + bC);
        __syncthreads();
        As[aK4 + 0][aRow0] = a0.x; As[aK4 + 1][aRow0] = a0.y;
        As[aK4 + 2][aRow0] = a0.z; As[aK4 + 3][aRow0] = a0.w;
        As[aK4 + 0][aRow0 + 64] = a1.x; As[aK4 + 1][aRow0 + 64] = a1.y;
        As[aK4 + 2][aRow0 + 64] = a1.z; As[aK4 + 3][aRow0 + 64] = a1.w;
        *(float4*)&Bs[bK][bC] = bv;
        __syncthreads();
        #pragma unroll
        for (int kk = 0; kk < 16; kk++) {
            float4 aA = *(const float4*)&As[kk][ty * 8];
            float4 aB = *(const float4*)&As[kk][ty * 8 + 4];
            float4 bb = *(const float4*)&Bs[kk][tx * 4];
            float ar[8] = {aA.x, aA.y, aA.z, aA.w, aB.x, aB.y, aB.z, aB.w};
            float bc[4] = {bb.x, bb.y, bb.z, bb.w};
            #pragma unroll
            for (int i = 0; i < 8; i++)
                #pragma unroll
                for (int j = 0; j < 4; j++) acc[i][j] = fmaf(ar[i], bc[j], acc[i][j]);
        }
    }

    __syncthreads();
    #pragma unroll
    for (int i = 0; i < 8; i++)
        #pragma unroll
        for (int j = 0; j < 4; j++)
            Cs[ty * 8 + i][tx * 4 + j] = acc[i][j] + bias[tx * 4 + j];
    __syncthreads();

    int rr = t >> 1, h = t & 1;
    const float* cb = &Cs[rr][h * 32];
    float ss = 0.0f;
    #pragma unroll
    for (int j = 0; j < 32; j++) ss += cb[j] * cb[j];
    ss += __shfl_xor_sync(0xffffffffu, ss, 1);
    float scl = INV_SQRT2 / fmaxf(sqrtf(ss), 1e-12f);
    int gr = rowbase + rr;
    if (gr < M) {
        float* op = outp + (size_t)gr * DIM + BR + h * 32;
        #pragma unroll
        for (int j = 0; j < 32; j += 4) {
            float4 v = *(const float4*)(cb + j);
            v.x *= scl; v.y *= scl; v.z *= scl; v.w *= scl;
            *(float4*)(op + j) = v;
        }
    }
}

// ---------------- scoring: block per batch row ----------------
__global__ void k_score(const int* __restrict__ pos_iids, const int* __restrict__ cand_ids) {
    __shared__ __align__(16) float su[128];
    __shared__ float sc[128];
    int b = blockIdx.x, t = threadIdx.x;
    su[t] = g_batch_u[(size_t)b * DIM + t];
    __syncthreads();
    int pos = pos_iids[b];
    int id = cand_ids[(size_t)b * NCAND + t];
    if (id == pos) id = (id + 1) % N_ITEMS;
    const float4* ip = (const float4*)(g_i_all + (size_t)id * DIM);
    const float4* us = (const float4*)su;
    float a = 0.0f;
    #pragma unroll
    for (int j = 0; j < 32; j++) {
        float4 iv = __ldg(ip + j);
        float4 uv = us[j];
        a += iv.x * uv.x + iv.y * uv.y + iv.z * uv.z + iv.w * uv.w;
    }
    sc[t] = a;
    __syncthreads();

    if (t < 32) {
        const float* pp = g_i_all + (size_t)pos * DIM;
        float p = pp[t] * su[t] + pp[t + 32] * su[t + 32] +
                  pp[t + 64] * su[t + 64] + pp[t + 96] * su[t + 96];
        #pragma unroll
        for (int off = 16; off > 0; off >>= 1) p += __shfl_xor_sync(0xffffffffu, p, off);

        float v0 = sc[t * 4], v1 = sc[t * 4 + 1], v2 = sc[t * 4 + 2], v3 = sc[t * 4 + 3];
        float Lmax = 0.0f, S = 0.0f;
        for (int it = 0; it < NNEG; it++) {
            float best = v0; int bq = 0;
            if (v1 > best) { best = v1; bq = 1; }
            if (v2 > best) { best = v2; bq = 2; }
            if (v3 > best) { best = v3; bq = 3; }
            float wb = best;
            #pragma unroll
            for (int off = 16; off > 0; off >>= 1) wb = fmaxf(wb, __shfl_xor_sync(0xffffffffu, wb, off));
            unsigned m = __ballot_sync(0xffffffffu, best == wb);
            int owner = __ffs(m) - 1;
            if (t == owner) {
                if (bq == 0) v0 = -3.0e38f;
                else if (bq == 1) v1 = -3.0e38f;
                else if (bq == 2) v2 = -3.0e38f;
                else v3 = -3.0e38f;
            }
            float l = wb * 10.0f;
            if (it == 0) { Lmax = l; S = 1.0f; }
            else S += __expf(l - Lmax);
        }
        float lp = p * 10.0f;
        if (lp > Lmax) { S = S * __expf(Lmax - lp) + 1.0f; Lmax = lp; }
        else S += __expf(lp - Lmax);
        float lossb = Lmax + logf(S) - lp;
        if (t == 0) atomicAdd(&g_loss, lossb);
    }
}

__global__ void k_final(float* out) {
    out[0] = g_loss * (1.0f / (float)BATCHB);
}

// ---------------- launch ----------------
extern "C" void kernel_launch(void* const* d_in, const int* in_sizes, int n_in,
                              void* d_out, int out_size) {
    const float* raw_item_embs = (const float*)d_in[0];
    const float* user_sem_base = (const float*)d_in[1];
    const float* sem_w         = (const float*)d_in[2];
    const float* sem_b         = (const float*)d_in[3];
    const float* collab_user_w = (const float*)d_in[4];
    const float* collab_item_w = (const float*)d_in[5];
    const float* adj_vals      = (const float*)d_in[6];
    const int*   adj_rows      = (const int*)d_in[7];
    const int*   adj_cols      = (const int*)d_in[8];
    const int*   uids          = (const int*)d_in[9];
    const int*   pos_iids      = (const int*)d_in[10];
    const int*   cand_ids      = (const int*)d_in[11];
    float* out = (float*)d_out;

    k_zero<<<(N_TOT + 255) / 256, 256>>>();
    k_init_ego<<<(N_TOT * BR + 255) / 256, 256>>>(collab_user_w, collab_item_w);

    // CSR build
    k_hist<<<NE / 256, 256>>>(adj_rows);
    k_scan1<<<NB_SCAN, 256>>>();
    k_scan2<<<1, 32>>>();
    k_scan3<<<NB_SCAN, 256>>>();
    k_scatter<<<NE / 256, 256>>>(adj_rows, adj_cols, adj_vals);

    // semantic halves (fp32 SIMT, proven)
    k_sem_gemm<false><<<(N_ITEMS + 127) / 128, 256>>>(raw_item_embs, sem_w, sem_b, nullptr, N_ITEMS);
    k_sem_gemm<true><<<BATCHB / 128, 256>>>(user_sem_base, sem_w, sem_b, uids, BATCHB);

    // 3 GCN layers; last layer fuses item normalization
    int spmm_blocks = (N_TOT * 32 + 255) / 256;
    k_spmm<false><<<spmm_blocks, 256>>>(0);   // a -> b
    k_spmm<false><<<spmm_blocks, 256>>>(1);   // b -> a
    k_spmm<true ><<<spmm_blocks, 256>>>(0);   // a -> (acc/i_all)

    k_collab_users<<<(BATCHB * 32 + 255) / 256, 256>>>(uids);

    k_score<<<BATCHB, 128>>>(pos_iids, cand_ids);
    k_final<<<1, 1>>>(out);
}

// round 6
// speedup vs baseline: 1.8005x; 1.8005x over previous
#include <cuda_runtime.h>
#include <cuda_bf16.h>
#include <math.h>
#include <stdint.h>

#define N_USERS 100000
#define N_ITEMS 50000
#define N_TOT   150000
#define IN_DIM  768
#define BR      64
#define NE      2097152
#define BATCHB  4096
#define NCAND   128
#define NNEG    16
#define DIM     128
#define INV_SQRT2 0.70710678118f
#define NB_SCAN 147
#define UMARK_WORDS ((N_USERS + 31) / 32)

// ---------------- scratch (device globals; NEVER referenced from host code) ----------------
__device__ float g_ego_a[(size_t)N_TOT * BR];
__device__ float g_ego_b[(size_t)N_TOT * BR];
__device__ float g_acc  [(size_t)N_TOT * BR];
__device__ float g_i_all[(size_t)N_ITEMS * DIM];
__device__ float g_batch_u[(size_t)BATCHB * DIM];
__device__ int   g_row_ptr[N_TOT + 1];
__device__ int   g_row_cnt[N_TOT];
__device__ int   g_row_fill[N_TOT];
__device__ int2  g_cv[NE];
__device__ int   g_bsum[256];
__device__ unsigned g_umark[UMARK_WORDS];
__device__ float g_loss;

// ---------------- fused init: zero counters + umark + loss, init ego/acc ----------------
__global__ void k_init(const float* __restrict__ uw, const float* __restrict__ iw) {
    int idx = blockIdx.x * blockDim.x + threadIdx.x;
    if (idx < N_TOT) { g_row_cnt[idx] = 0; g_row_fill[idx] = 0; }
    if (idx < UMARK_WORDS) g_umark[idx] = 0u;
    if (idx == 0) g_loss = 0.0f;
    if (idx < N_TOT * BR) {
        int row = idx >> 6, c = idx & 63;
        float v = (row < N_USERS) ? uw[row * BR + c] : iw[(row - N_USERS) * BR + c];
        g_ego_a[idx] = v;
        g_acc[idx]   = v;
    }
}

__global__ void k_mark(const int* __restrict__ uids) {
    int i = blockIdx.x * blockDim.x + threadIdx.x;
    if (i < BATCHB) {
        int u = uids[i];
        atomicOr(&g_umark[u >> 5], 1u << (u & 31));
    }
}

// ---------------- CSR build ----------------
__global__ void k_hist(const int* __restrict__ rows) {
    int i = blockIdx.x * blockDim.x + threadIdx.x;
    if (i < NE) atomicAdd(&g_row_cnt[rows[i]], 1);
}

__global__ void k_scan1() {
    __shared__ int red[256];
    int b = blockIdx.x, t = threadIdx.x;
    int base = b * 1024 + t * 4;
    int s = 0;
    #pragma unroll
    for (int q = 0; q < 4; q++) { int i = base + q; if (i < N_TOT) s += g_row_cnt[i]; }
    red[t] = s; __syncthreads();
    for (int off = 128; off > 0; off >>= 1) {
        if (t < off) red[t] += red[t + off];
        __syncthreads();
    }
    if (t == 0) g_bsum[b] = red[0];
}

__global__ void k_scan2() {
    if (threadIdx.x == 0 && blockIdx.x == 0) {
        int run = 0;
        for (int i = 0; i < NB_SCAN; i++) { int t = g_bsum[i]; g_bsum[i] = run; run += t; }
    }
}

__global__ void k_scan3() {
    __shared__ int tsum[256];
    int b = blockIdx.x, t = threadIdx.x;
    int base = b * 1024 + t * 4;
    int c0 = 0, c1 = 0, c2 = 0, c3 = 0;
    if (base + 0 < N_TOT) c0 = g_row_cnt[base + 0];
    if (base + 1 < N_TOT) c1 = g_row_cnt[base + 1];
    if (base + 2 < N_TOT) c2 = g_row_cnt[base + 2];
    if (base + 3 < N_TOT) c3 = g_row_cnt[base + 3];
    int p1 = c0, p2 = c0 + c1, p3 = c0 + c1 + c2, s = p3 + c3;
    tsum[t] = s; __syncthreads();
    for (int off = 1; off < 256; off <<= 1) {
        int v = (t >= off) ? tsum[t - off] : 0;
        __syncthreads();
        tsum[t] += v;
        __syncthreads();
    }
    int excl = tsum[t] - s + g_bsum[b];
    if (base + 0 < N_TOT) g_row_ptr[base + 0] = excl;
    if (base + 1 < N_TOT) g_row_ptr[base + 1] = excl + p1;
    if (base + 2 < N_TOT) g_row_ptr[base + 2] = excl + p2;
    if (base + 3 < N_TOT) g_row_ptr[base + 3] = excl + p3;
    if (b == 0 && t == 0) g_row_ptr[N_TOT] = NE;
}

__global__ void k_scatter(const int* __restrict__ rows, const int* __restrict__ cols,
                          const float* __restrict__ vals) {
    int i = blockIdx.x * blockDim.x + threadIdx.x;
    if (i >= NE) return;
    int r = rows[i];
    int ofs = atomicAdd(&g_row_fill[r], 1);
    g_cv[g_row_ptr[r] + ofs] = make_int2(cols[i], __float_as_int(vals[i]));
}

// ---------------- SpMM: warp per destination row, inner unroll x4 ----------------
template<bool LAST>
__global__ void k_spmm(int phase) {
    const float* __restrict__ in = (phase & 1) ? g_ego_b : g_ego_a;
    float* __restrict__ outp     = (phase & 1) ? g_ego_a : g_ego_b;
    int w = (blockIdx.x * blockDim.x + threadIdx.x) >> 5;
    int lane = threadIdx.x & 31;
    if (w >= N_TOT) return;
    // layer-3 user rows only matter for the 4096 batch uids
    if (LAST && w < N_USERS && !((g_umark[w >> 5] >> (w & 31)) & 1u)) return;

    int s = g_row_ptr[w], e = g_row_ptr[w + 1];
    float a0 = 0.0f, a1 = 0.0f;
    for (int base = s; base < e; base += 32) {
        int idx = base + lane;
        int c = 0; float v = 0.0f;
        if (idx < e) { int2 cv = __ldg(&g_cv[idx]); c = cv.x; v = __int_as_float(cv.y); }
        int cnt = min(32, e - base);
        int cnt4 = (cnt + 3) & ~3;   // tail lanes have v=0 -> exact no-ops
        for (int j = 0; j < cnt4; j += 4) {
            int cc0 = __shfl_sync(0xffffffffu, c, j);
            int cc1 = __shfl_sync(0xffffffffu, c, j + 1);
            int cc2 = __shfl_sync(0xffffffffu, c, j + 2);
            int cc3 = __shfl_sync(0xffffffffu, c, j + 3);
            float vv0 = __shfl_sync(0xffffffffu, v, j);
            float vv1 = __shfl_sync(0xffffffffu, v, j + 1);
            float vv2 = __shfl_sync(0xffffffffu, v, j + 2);
            float vv3 = __shfl_sync(0xffffffffu, v, j + 3);
            float2 p0 = __ldg((const float2*)(in + (size_t)cc0 * BR) + lane);
            float2 p1 = __ldg((const float2*)(in + (size_t)cc1 * BR) + lane);
            float2 p2 = __ldg((const float2*)(in + (size_t)cc2 * BR) + lane);
            float2 p3 = __ldg((const float2*)(in + (size_t)cc3 * BR) + lane);
            a0 = fmaf(vv0, p0.x, a0); a1 = fmaf(vv0, p0.y, a1);
            a0 = fmaf(vv1, p1.x, a0); a1 = fmaf(vv1, p1.y, a1);
            a0 = fmaf(vv2, p2.x, a0); a1 = fmaf(vv2, p2.y, a1);
            a0 = fmaf(vv3, p3.x, a0); a1 = fmaf(vv3, p3.y, a1);
        }
    }
    size_t o = (size_t)w * BR + 2 * lane;
    if (!LAST) {
        outp[o] = a0; outp[o + 1] = a1;
        g_acc[o] += a0; g_acc[o + 1] += a1;
    } else {
        float t0 = g_acc[o] + a0, t1 = g_acc[o + 1] + a1;
        if (w < N_USERS) {
            g_acc[o] = t0; g_acc[o + 1] = t1;   // read by k_collab_users
        } else {
            float ss = t0 * t0 + t1 * t1;
            #pragma unroll
            for (int off = 16; off > 0; off >>= 1) ss += __shfl_xor_sync(0xffffffffu, ss, off);
            float sc = INV_SQRT2 / fmaxf(sqrtf(ss), 1e-12f);
            size_t oi = (size_t)(w - N_USERS) * DIM + 2 * lane;
            g_i_all[oi] = t0 * sc; g_i_all[oi + 1] = t1 * sc;
        }
    }
}

__global__ void k_collab_users(const int* __restrict__ uids) {
    int w = (blockIdx.x * blockDim.x + threadIdx.x) >> 5;
    int lane = threadIdx.x & 31;
    if (w >= BATCHB) return;
    int u = uids[w];
    size_t o = (size_t)u * BR;
    float v0 = g_acc[o + lane], v1 = g_acc[o + lane + 32];
    float ss = v0 * v0 + v1 * v1;
    #pragma unroll
    for (int off = 16; off > 0; off >>= 1) ss += __shfl_xor_sync(0xffffffffu, ss, off);
    float sc = INV_SQRT2 / fmaxf(sqrtf(ss), 1e-12f);
    g_batch_u[(size_t)w * DIM + lane] = v0 * sc;
    g_batch_u[(size_t)w * DIM + lane + 32] = v1 * sc;
}

// ---------------- split-bf16 mma.sync semantic GEMM (R4-proven) ----------------
#define KC 64
#define KP 72
#define NCHUNKS (IN_DIM / KC)
#define SA_H 0
#define SA_L (128 * KP)
#define SB_H (2 * 128 * KP)
#define SB_L (2 * 128 * KP + 64 * KP)
#define SM_U16_TOTAL (2 * 128 * KP + 2 * 64 * KP)
#define SM_BYTES (SM_U16_TOTAL * 2)

__device__ __forceinline__ void mma_bf16(float* d, uint32_t a0, uint32_t a1, uint32_t a2,
                                         uint32_t a3, uint32_t b0, uint32_t b1) {
    asm volatile("mma.sync.aligned.m16n8k16.row.col.f32.bf16.bf16.f32 "
                 "{%0,%1,%2,%3}, {%4,%5,%6,%7}, {%8,%9}, {%0,%1,%2,%3};"
                 : "+f"(d[0]), "+f"(d[1]), "+f"(d[2]), "+f"(d[3])
                 : "r"(a0), "r"(a1), "r"(a2), "r"(a3), "r"(b0), "r"(b1));
}

__device__ __forceinline__ void split2(float x, float y, uint32_t& hi, uint32_t& lo) {
    uint32_t xi = __float_as_uint(x), yi = __float_as_uint(y);
    hi = __byte_perm(xi, yi, 0x7632);
    float lx = x - __uint_as_float(xi & 0xFFFF0000u);
    float ly = y - __uint_as_float(yi & 0xFFFF0000u);
    __nv_bfloat162 p = __floats2bfloat162_rn(lx, ly);
    lo = *(uint32_t*)&p;
}

template<bool GATHER>
__global__ void __launch_bounds__(256) k_sem_mma(const float* __restrict__ A,
                                                 const float* __restrict__ W,
                                                 const float* __restrict__ bias,
                                                 const int* __restrict__ gidx, int M) {
    extern __shared__ uint16_t sm[];
    float* __restrict__ outp = GATHER ? g_batch_u : g_i_all;
    int t = threadIdx.x, wid = t >> 5, lane = t & 31;
    int rowbase = blockIdx.x * 128;

    int ar = t >> 1, kh = (t & 1) * 32;
    int gr = rowbase + ar;
    bool av = gr < M;
    int srow = av ? (GATHER ? __ldg(gidx + gr) : gr) : 0;
    const float* arp = A + (size_t)srow * IN_DIM;

    int bn = t & 63, bk0 = t >> 6;

    float acc[8][4];
    #pragma unroll
    for (int i = 0; i < 8; i++)
        #pragma unroll
        for (int j = 0; j < 4; j++) acc[i][j] = 0.0f;

    int mr = wid * 16;
    int r0 = mr + (lane >> 2);
    int kq0 = (lane & 3) * 2;

    for (int ch = 0; ch < NCHUNKS; ch++) {
        int k0 = ch * KC;
        __syncthreads();
        #pragma unroll
        for (int i = 0; i < 8; i++) {
            int k = kh + i * 4;
            float4 a = av ? __ldg((const float4*)(arp + k0 + k)) : make_float4(0, 0, 0, 0);
            uint32_t h01, l01, h23, l23;
            split2(a.x, a.y, h01, l01);
            split2(a.z, a.w, h23, l23);
            int o = ar * KP + k;
            *(uint32_t*)(sm + SA_H + o)     = h01;
            *(uint32_t*)(sm + SA_H + o + 2) = h23;
            *(uint32_t*)(sm + SA_L + o)     = l01;
            *(uint32_t*)(sm + SA_L + o + 2) = l23;
        }
        #pragma unroll
        for (int i = 0; i < 16; i++) {
            int k = bk0 + i * 4;
            float wv = __ldg(W + (size_t)(k0 + k) * BR + bn);
            uint32_t wi = __float_as_uint(wv);
            float lo = wv - __uint_as_float(wi & 0xFFFF0000u);
            __nv_bfloat16 bl = __float2bfloat16(lo);
            int o = bn * KP + k;
            sm[SB_H + o] = (uint16_t)(wi >> 16);
            sm[SB_L + o] = *(uint16_t*)&bl;
        }
        __syncthreads();
        #pragma unroll
        for (int ks = 0; ks < 4; ks++) {
            int kq = ks * 16 + kq0;
            const uint16_t* pah = sm + SA_H + kq;
            const uint16_t* pal = sm + SA_L + kq;
            uint32_t ah0 = *(const uint32_t*)(pah + r0 * KP);
            uint32_t ah1 = *(const uint32_t*)(pah + (r0 + 8) * KP);
            uint32_t ah2 = *(const uint32_t*)(pah + r0 * KP + 8);
            uint32_t ah3 = *(const uint32_t*)(pah + (r0 + 8) * KP + 8);
            uint32_t al0 = *(const uint32_t*)(pal + r0 * KP);
            uint32_t al1 = *(const uint32_t*)(pal + (r0 + 8) * KP);
            uint32_t al2 = *(const uint32_t*)(pal + r0 * KP + 8);
            uint32_t al3 = *(const uint32_t*)(pal + (r0 + 8) * KP + 8);
            #pragma unroll
            for (int nt = 0; nt < 8; nt++) {
                int n = nt * 8 + (lane >> 2);
                uint32_t bh0 = *(const uint32_t*)(sm + SB_H + n * KP + kq);
                uint32_t bh1 = *(const uint32_t*)(sm + SB_H + n * KP + kq + 8);
                uint32_t bl0 = *(const uint32_t*)(sm + SB_L + n * KP + kq);
                uint32_t bl1 = *(const uint32_t*)(sm + SB_L + n * KP + kq + 8);
                mma_bf16(acc[nt], ah0, ah1, ah2, ah3, bh0, bh1);
                mma_bf16(acc[nt], ah0, ah1, ah2, ah3, bl0, bl1);
                mma_bf16(acc[nt], al0, al1, al2, al3, bh0, bh1);
            }
        }
    }

    float ss0 = 0.0f, ss1 = 0.0f;
    #pragma unroll
    for (int nt = 0; nt < 8; nt++) {
        int c = nt * 8 + (lane & 3) * 2;
        float b0 = __ldg(bias + c), b1 = __ldg(bias + c + 1);
        acc[nt][0] += b0; acc[nt][1] += b1;
        acc[nt][2] += b0; acc[nt][3] += b1;
        ss0 += acc[nt][0] * acc[nt][0] + acc[nt][1] * acc[nt][1];
        ss1 += acc[nt][2] * acc[nt][2] + acc[nt][3] * acc[nt][3];
    }
    ss0 += __shfl_xor_sync(0xffffffffu, ss0, 1);
    ss0 += __shfl_xor_sync(0xffffffffu, ss0, 2);
    ss1 += __shfl_xor_sync(0xffffffffu, ss1, 1);
    ss1 += __shfl_xor_sync(0xffffffffu, ss1, 2);
    float sc0 = INV_SQRT2 / fmaxf(sqrtf(ss0), 1e-12f);
    float sc1 = INV_SQRT2 / fmaxf(sqrtf(ss1), 1e-12f);
    int gr0 = rowbase + r0, gr1 = gr0 + 8;
    #pragma unroll
    for (int nt = 0; nt < 8; nt++) {
        int c = nt * 8 + (lane & 3) * 2;
        if (gr0 < M)
            *(float2*)(outp + (size_t)gr0 * DIM + BR + c) =
                make_float2(acc[nt][0] * sc0, acc[nt][1] * sc0);
        if (gr1 < M)
            *(float2*)(outp + (size_t)gr1 * DIM + BR + c) =
                make_float2(acc[nt][2] * sc1, acc[nt][3] * sc1);
    }
}

// ---------------- scoring: block per batch row ----------------
__global__ void k_score(const int* __restrict__ pos_iids, const int* __restrict__ cand_ids) {
    __shared__ __align__(16) float su[128];
    __shared__ float sc[128];
    int b = blockIdx.x, t = threadIdx.x;
    su[t] = g_batch_u[(size_t)b * DIM + t];
    __syncthreads();
    int pos = pos_iids[b];
    int id = cand_ids[(size_t)b * NCAND + t];
    if (id == pos) id = (id + 1) % N_ITEMS;
    const float4* ip = (const float4*)(g_i_all + (size_t)id * DIM);
    const float4* us = (const float4*)su;
    float a = 0.0f;
    #pragma unroll
    for (int j = 0; j < 32; j++) {
        float4 iv = __ldg(ip + j);
        float4 uv = us[j];
        a += iv.x * uv.x + iv.y * uv.y + iv.z * uv.z + iv.w * uv.w;
    }
    sc[t] = a;
    __syncthreads();

    if (t < 32) {
        const float* pp = g_i_all + (size_t)pos * DIM;
        float p = pp[t] * su[t] + pp[t + 32] * su[t + 32] +
                  pp[t + 64] * su[t + 64] + pp[t + 96] * su[t + 96];
        #pragma unroll
        for (int off = 16; off > 0; off >>= 1) p += __shfl_xor_sync(0xffffffffu, p, off);

        float v0 = sc[t * 4], v1 = sc[t * 4 + 1], v2 = sc[t * 4 + 2], v3 = sc[t * 4 + 3];
        float Lmax = 0.0f, S = 0.0f;
        for (int it = 0; it < NNEG; it++) {
            float best = v0; int bq = 0;
            if (v1 > best) { best = v1; bq = 1; }
            if (v2 > best) { best = v2; bq = 2; }
            if (v3 > best) { best = v3; bq = 3; }
            float wb = best;
            #pragma unroll
            for (int off = 16; off > 0; off >>= 1) wb = fmaxf(wb, __shfl_xor_sync(0xffffffffu, wb, off));
            unsigned m = __ballot_sync(0xffffffffu, best == wb);
            int owner = __ffs(m) - 1;
            if (t == owner) {
                if (bq == 0) v0 = -3.0e38f;
                else if (bq == 1) v1 = -3.0e38f;
                else if (bq == 2) v2 = -3.0e38f;
                else v3 = -3.0e38f;
            }
            float l = wb * 10.0f;
            if (it == 0) { Lmax = l; S = 1.0f; }
            else S += __expf(l - Lmax);
        }
        float lp = p * 10.0f;
        if (lp > Lmax) { S = S * __expf(Lmax - lp) + 1.0f; Lmax = lp; }
        else S += __expf(lp - Lmax);
        float lossb = Lmax + logf(S) - lp;
        if (t == 0) atomicAdd(&g_loss, lossb);
    }
}

__global__ void k_final(float* out) {
    out[0] = g_loss * (1.0f / (float)BATCHB);
}

// ---------------- launch ----------------
extern "C" void kernel_launch(void* const* d_in, const int* in_sizes, int n_in,
                              void* d_out, int out_size) {
    const float* raw_item_embs = (const float*)d_in[0];
    const float* user_sem_base = (const float*)d_in[1];
    const float* sem_w         = (const float*)d_in[2];
    const float* sem_b         = (const float*)d_in[3];
    const float* collab_user_w = (const float*)d_in[4];
    const float* collab_item_w = (const float*)d_in[5];
    const float* adj_vals      = (const float*)d_in[6];
    const int*   adj_rows      = (const int*)d_in[7];
    const int*   adj_cols      = (const int*)d_in[8];
    const int*   uids          = (const int*)d_in[9];
    const int*   pos_iids      = (const int*)d_in[10];
    const int*   cand_ids      = (const int*)d_in[11];
    float* out = (float*)d_out;

    cudaFuncSetAttribute(k_sem_mma<false>, cudaFuncAttributeMaxDynamicSharedMemorySize, SM_BYTES);
    cudaFuncSetAttribute(k_sem_mma<true>,  cudaFuncAttributeMaxDynamicSharedMemorySize, SM_BYTES);

    k_init<<<(N_TOT * BR + 255) / 256, 256>>>(collab_user_w, collab_item_w);
    k_mark<<<(BATCHB + 255) / 256, 256>>>(uids);

    // CSR build
    k_hist<<<NE / 256, 256>>>(adj_rows);
    k_scan1<<<NB_SCAN, 256>>>();
    k_scan2<<<1, 32>>>();
    k_scan3<<<NB_SCAN, 256>>>();
    k_scatter<<<NE / 256, 256>>>(adj_rows, adj_cols, adj_vals);

    // semantic halves on HMMA tensor cores
    k_sem_mma<false><<<(N_ITEMS + 127) / 128, 256, SM_BYTES>>>(raw_item_embs, sem_w, sem_b,
                                                               nullptr, N_ITEMS);
    k_sem_mma<true><<<BATCHB / 128, 256, SM_BYTES>>>(user_sem_base, sem_w, sem_b, uids, BATCHB);

    // 3 GCN layers; layer 3 fuses item normalize + skips non-batch users
    int spmm_blocks = (N_TOT * 32 + 255) / 256;
    k_spmm<false><<<spmm_blocks, 256>>>(0);   // a -> b
    k_spmm<false><<<spmm_blocks, 256>>>(1);   // b -> a
    k_spmm<true ><<<spmm_blocks, 256>>>(0);   // a -> (acc/i_all), masked users

    k_collab_users<<<(BATCHB * 32 + 255) / 256, 256>>>(uids);

    k_score<<<BATCHB, 128>>>(pos_iids, cand_ids);
    k_final<<<1, 1>>>(out);
}

// round 7
// speedup vs baseline: 2.3762x; 1.3198x over previous
#include <cuda_runtime.h>
#include <cuda_bf16.h>
#include <math.h>
#include <stdint.h>

#define N_USERS 100000
#define N_ITEMS 50000
#define N_TOT   150000
#define IN_DIM  768
#define BR      64
#define NE      2097152
#define BATCHB  4096
#define NCAND   128
#define NNEG    16
#define DIM     128
#define INV_SQRT2 0.70710678118f
#define NB_SCAN 147
#define UMARK_WORDS ((N_USERS + 31) / 32)

// ---------------- scratch (device globals; NEVER referenced from host code) ----------------
__device__ float g_l1   [(size_t)N_TOT * BR];   // layer-1 output
__device__ float g_l2   [(size_t)N_TOT * BR];   // layer-2 output
__device__ float g_acc  [(size_t)N_TOT * BR];   // only marked-user rows written (layer 3)
__device__ float g_i_all[(size_t)N_ITEMS * DIM];
__device__ float g_batch_u[(size_t)BATCHB * DIM];
__device__ int   g_row_ptr[N_TOT + 1];
__device__ int   g_row_cnt[N_TOT];
__device__ int   g_row_fill[N_TOT];
__device__ int2  g_cv[NE];
__device__ int   g_bsum[256];
__device__ unsigned g_umark[UMARK_WORDS];
__device__ float g_loss;

// ---------------- zero counters / marks ----------------
__global__ void k_zero() {
    int i = blockIdx.x * blockDim.x + threadIdx.x;
    if (i < N_TOT) { g_row_cnt[i] = 0; g_row_fill[i] = 0; }
    if (i < UMARK_WORDS) g_umark[i] = 0u;
    if (i == 0) g_loss = 0.0f;
}

__global__ void k_mark(const int* __restrict__ uids) {
    int i = blockIdx.x * blockDim.x + threadIdx.x;
    if (i < BATCHB) {
        int u = uids[i];
        atomicOr(&g_umark[u >> 5], 1u << (u & 31));
    }
}

// ---------------- CSR build ----------------
__global__ void k_hist(const int* __restrict__ rows) {
    int i = blockIdx.x * blockDim.x + threadIdx.x;
    if (i < NE) atomicAdd(&g_row_cnt[rows[i]], 1);
}

__global__ void k_scan1() {
    __shared__ int red[256];
    int b = blockIdx.x, t = threadIdx.x;
    int base = b * 1024 + t * 4;
    int s = 0;
    #pragma unroll
    for (int q = 0; q < 4; q++) { int i = base + q; if (i < N_TOT) s += g_row_cnt[i]; }
    red[t] = s; __syncthreads();
    for (int off = 128; off > 0; off >>= 1) {
        if (t < off) red[t] += red[t + off];
        __syncthreads();
    }
    if (t == 0) g_bsum[b] = red[0];
}

__global__ void k_scan2() {
    if (threadIdx.x == 0 && blockIdx.x == 0) {
        int run = 0;
        for (int i = 0; i < NB_SCAN; i++) { int t = g_bsum[i]; g_bsum[i] = run; run += t; }
    }
}

__global__ void k_scan3() {
    __shared__ int tsum[256];
    int b = blockIdx.x, t = threadIdx.x;
    int base = b * 1024 + t * 4;
    int c0 = 0, c1 = 0, c2 = 0, c3 = 0;
    if (base + 0 < N_TOT) c0 = g_row_cnt[base + 0];
    if (base + 1 < N_TOT) c1 = g_row_cnt[base + 1];
    if (base + 2 < N_TOT) c2 = g_row_cnt[base + 2];
    if (base + 3 < N_TOT) c3 = g_row_cnt[base + 3];
    int p1 = c0, p2 = c0 + c1, p3 = c0 + c1 + c2, s = p3 + c3;
    tsum[t] = s; __syncthreads();
    for (int off = 1; off < 256; off <<= 1) {
        int v = (t >= off) ? tsum[t - off] : 0;
        __syncthreads();
        tsum[t] += v;
        __syncthreads();
    }
    int excl = tsum[t] - s + g_bsum[b];
    if (base + 0 < N_TOT) g_row_ptr[base + 0] = excl;
    if (base + 1 < N_TOT) g_row_ptr[base + 1] = excl + p1;
    if (base + 2 < N_TOT) g_row_ptr[base + 2] = excl + p2;
    if (base + 3 < N_TOT) g_row_ptr[base + 3] = excl + p3;
    if (b == 0 && t == 0) g_row_ptr[N_TOT] = NE;
}

__global__ void k_scatter(const int* __restrict__ rows, const int* __restrict__ cols,
                          const float* __restrict__ vals) {
    int i = blockIdx.x * blockDim.x + threadIdx.x;
    if (i >= NE) return;
    int r = rows[i];
    int ofs = atomicAdd(&g_row_fill[r], 1);
    g_cv[g_row_ptr[r] + ofs] = make_int2(cols[i], __float_as_int(vals[i]));
}

// ---------------- SpMM: warp per destination row ----------------
// MODE 0: gather raw(uw/iw) -> g_l1
// MODE 1: gather g_l1       -> g_l2
// MODE 2: gather g_l2; epilogue acc = raw + l1 + l2 + l3; items -> g_i_all (normalized),
//         marked users -> g_acc. Unmarked users skipped.
template<int MODE>
__global__ void k_spmm(const float* __restrict__ uw, const float* __restrict__ iw) {
    int w = (blockIdx.x * blockDim.x + threadIdx.x) >> 5;
    int lane = threadIdx.x & 31;
    if (w >= N_TOT) return;
    if (MODE == 2 && w < N_USERS && !((g_umark[w >> 5] >> (w & 31)) & 1u)) return;

    int s = g_row_ptr[w], e = g_row_ptr[w + 1];
    float a0 = 0.0f, a1 = 0.0f;
    for (int base = s; base < e; base += 32) {
        int idx = base + lane;
        int c = 0; float v = 0.0f;
        if (idx < e) { int2 cv = __ldg(&g_cv[idx]); c = cv.x; v = __int_as_float(cv.y); }
        int cnt = min(32, e - base);
        int cnt4 = (cnt + 3) & ~3;   // tail lanes have v=0 -> exact no-ops
        for (int j = 0; j < cnt4; j += 4) {
            int cc0 = __shfl_sync(0xffffffffu, c, j);
            int cc1 = __shfl_sync(0xffffffffu, c, j + 1);
            int cc2 = __shfl_sync(0xffffffffu, c, j + 2);
            int cc3 = __shfl_sync(0xffffffffu, c, j + 3);
            float vv0 = __shfl_sync(0xffffffffu, v, j);
            float vv1 = __shfl_sync(0xffffffffu, v, j + 1);
            float vv2 = __shfl_sync(0xffffffffu, v, j + 2);
            float vv3 = __shfl_sync(0xffffffffu, v, j + 3);
            const float *b0, *b1, *b2, *b3;
            if (MODE == 0) {
                b0 = (cc0 < N_USERS) ? uw + (size_t)cc0 * BR : iw + (size_t)(cc0 - N_USERS) * BR;
                b1 = (cc1 < N_USERS) ? uw + (size_t)cc1 * BR : iw + (size_t)(cc1 - N_USERS) * BR;
                b2 = (cc2 < N_USERS) ? uw + (size_t)cc2 * BR : iw + (size_t)(cc2 - N_USERS) * BR;
                b3 = (cc3 < N_USERS) ? uw + (size_t)cc3 * BR : iw + (size_t)(cc3 - N_USERS) * BR;
            } else {
                const float* in = (MODE == 1) ? g_l1 : g_l2;
                b0 = in + (size_t)cc0 * BR;
                b1 = in + (size_t)cc1 * BR;
                b2 = in + (size_t)cc2 * BR;
                b3 = in + (size_t)cc3 * BR;
            }
            float2 p0 = __ldg((const float2*)b0 + lane);
            float2 p1 = __ldg((const float2*)b1 + lane);
            float2 p2 = __ldg((const float2*)b2 + lane);
            float2 p3 = __ldg((const float2*)b3 + lane);
            a0 = fmaf(vv0, p0.x, a0); a1 = fmaf(vv0, p0.y, a1);
            a0 = fmaf(vv1, p1.x, a0); a1 = fmaf(vv1, p1.y, a1);
            a0 = fmaf(vv2, p2.x, a0); a1 = fmaf(vv2, p2.y, a1);
            a0 = fmaf(vv3, p3.x, a0); a1 = fmaf(vv3, p3.y, a1);
        }
    }
    size_t o = (size_t)w * BR + 2 * lane;
    if (MODE == 0) {
        g_l1[o] = a0; g_l1[o + 1] = a1;
    } else if (MODE == 1) {
        g_l2[o] = a0; g_l2[o + 1] = a1;
    } else {
        // acc = raw + l1 + l2 + l3
        const float* rp = (w < N_USERS) ? uw + (size_t)w * BR : iw + (size_t)(w - N_USERS) * BR;
        float2 r  = __ldg((const float2*)rp + lane);
        float2 x1 = *((const float2*)(g_l1 + (size_t)w * BR) + lane);
        float2 x2 = *((const float2*)(g_l2 + (size_t)w * BR) + lane);
        float t0 = r.x + x1.x + x2.x + a0;
        float t1 = r.y + x1.y + x2.y + a1;
        if (w < N_USERS) {
            g_acc[o] = t0; g_acc[o + 1] = t1;   // read by k_collab_users
        } else {
            float ss = t0 * t0 + t1 * t1;
            #pragma unroll
            for (int off = 16; off > 0; off >>= 1) ss += __shfl_xor_sync(0xffffffffu, ss, off);
            float sc = INV_SQRT2 / fmaxf(sqrtf(ss), 1e-12f);
            size_t oi = (size_t)(w - N_USERS) * DIM + 2 * lane;
            g_i_all[oi] = t0 * sc; g_i_all[oi + 1] = t1 * sc;
        }
    }
}

__global__ void k_collab_users(const int* __restrict__ uids) {
    int w = (blockIdx.x * blockDim.x + threadIdx.x) >> 5;
    int lane = threadIdx.x & 31;
    if (w >= BATCHB) return;
    int u = uids[w];
    size_t o = (size_t)u * BR;
    float v0 = g_acc[o + lane], v1 = g_acc[o + lane + 32];
    float ss = v0 * v0 + v1 * v1;
    #pragma unroll
    for (int off = 16; off > 0; off >>= 1) ss += __shfl_xor_sync(0xffffffffu, ss, off);
    float sc = INV_SQRT2 / fmaxf(sqrtf(ss), 1e-12f);
    g_batch_u[(size_t)w * DIM + lane] = v0 * sc;
    g_batch_u[(size_t)w * DIM + lane + 32] = v1 * sc;
}

// ---------------- split-bf16 mma.sync semantic GEMM ----------------
#define KC 64
#define KP 72
#define NCHUNKS (IN_DIM / KC)
#define SA_H 0
#define SA_L (128 * KP)
#define SB_H (2 * 128 * KP)
#define SB_L (2 * 128 * KP + 64 * KP)
#define SM_U16_TOTAL (2 * 128 * KP + 2 * 64 * KP)
#define SM_BYTES (SM_U16_TOTAL * 2)

__device__ __forceinline__ void mma_bf16(float* d, uint32_t a0, uint32_t a1, uint32_t a2,
                                         uint32_t a3, uint32_t b0, uint32_t b1) {
    asm volatile("mma.sync.aligned.m16n8k16.row.col.f32.bf16.bf16.f32 "
                 "{%0,%1,%2,%3}, {%4,%5,%6,%7}, {%8,%9}, {%0,%1,%2,%3};"
                 : "+f"(d[0]), "+f"(d[1]), "+f"(d[2]), "+f"(d[3])
                 : "r"(a0), "r"(a1), "r"(a2), "r"(a3), "r"(b0), "r"(b1));
}

__device__ __forceinline__ void split2(float x, float y, uint32_t& hi, uint32_t& lo) {
    uint32_t xi = __float_as_uint(x), yi = __float_as_uint(y);
    hi = __byte_perm(xi, yi, 0x7632);
    float lx = x - __uint_as_float(xi & 0xFFFF0000u);
    float ly = y - __uint_as_float(yi & 0xFFFF0000u);
    __nv_bfloat162 p = __floats2bfloat162_rn(lx, ly);
    lo = *(uint32_t*)&p;
}

template<bool GATHER>
__global__ void __launch_bounds__(256) k_sem_mma(const float* __restrict__ A,
                                                 const float* __restrict__ W,
                                                 const float* __restrict__ bias,
                                                 const int* __restrict__ gidx, int M) {
    extern __shared__ uint16_t sm[];
    float* __restrict__ outp = GATHER ? g_batch_u : g_i_all;
    int t = threadIdx.x, wid = t >> 5, lane = t & 31;
    int rowbase = blockIdx.x * 128;

    int ar = t >> 1, kh = (t & 1) * 32;
    int gr = rowbase + ar;
    bool av = gr < M;
    int srow = av ? (GATHER ? __ldg(gidx + gr) : gr) : 0;
    const float* arp = A + (size_t)srow * IN_DIM;

    int bn = t & 63, bk0 = t >> 6;

    float acc[8][4];
    #pragma unroll
    for (int i = 0; i < 8; i++)
        #pragma unroll
        for (int j = 0; j < 4; j++) acc[i][j] = 0.0f;

    int mr = wid * 16;
    int r0 = mr + (lane >> 2);
    int kq0 = (lane & 3) * 2;

    for (int ch = 0; ch < NCHUNKS; ch++) {
        int k0 = ch * KC;
        __syncthreads();
        #pragma unroll
        for (int i = 0; i < 8; i++) {
            int k = kh + i * 4;
            float4 a = av ? __ldg((const float4*)(arp + k0 + k)) : make_float4(0, 0, 0, 0);
            uint32_t h01, l01, h23, l23;
            split2(a.x, a.y, h01, l01);
            split2(a.z, a.w, h23, l23);
            int o = ar * KP + k;
            *(uint32_t*)(sm + SA_H + o)     = h01;
            *(uint32_t*)(sm + SA_H + o + 2) = h23;
            *(uint32_t*)(sm + SA_L + o)     = l01;
            *(uint32_t*)(sm + SA_L + o + 2) = l23;
        }
        #pragma unroll
        for (int i = 0; i < 16; i++) {
            int k = bk0 + i * 4;
            float wv = __ldg(W + (size_t)(k0 + k) * BR + bn);
            uint32_t wi = __float_as_uint(wv);
            float lo = wv - __uint_as_float(wi & 0xFFFF0000u);
            __nv_bfloat16 bl = __float2bfloat16(lo);
            int o = bn * KP + k;
            sm[SB_H + o] = (uint16_t)(wi >> 16);
            sm[SB_L + o] = *(uint16_t*)&bl;
        }
        __syncthreads();
        #pragma unroll
        for (int ks = 0; ks < 4; ks++) {
            int kq = ks * 16 + kq0;
            const uint16_t* pah = sm + SA_H + kq;
            const uint16_t* pal = sm + SA_L + kq;
            uint32_t ah0 = *(const uint32_t*)(pah + r0 * KP);
            uint32_t ah1 = *(const uint32_t*)(pah + (r0 + 8) * KP);
            uint32_t ah2 = *(const uint32_t*)(pah + r0 * KP + 8);
            uint32_t ah3 = *(const uint32_t*)(pah + (r0 + 8) * KP + 8);
            uint32_t al0 = *(const uint32_t*)(pal + r0 * KP);
            uint32_t al1 = *(const uint32_t*)(pal + (r0 + 8) * KP);
            uint32_t al2 = *(const uint32_t*)(pal + r0 * KP + 8);
            uint32_t al3 = *(const uint32_t*)(pal + (r0 + 8) * KP + 8);
            #pragma unroll
            for (int nt = 0; nt < 8; nt++) {
                int n = nt * 8 + (lane >> 2);
                uint32_t bh0 = *(const uint32_t*)(sm + SB_H + n * KP + kq);
                uint32_t bh1 = *(const uint32_t*)(sm + SB_H + n * KP + kq + 8);
                uint32_t bl0 = *(const uint32_t*)(sm + SB_L + n * KP + kq);
                uint32_t bl1 = *(const uint32_t*)(sm + SB_L + n * KP + kq + 8);
                mma_bf16(acc[nt], ah0, ah1, ah2, ah3, bh0, bh1);
                mma_bf16(acc[nt], ah0, ah1, ah2, ah3, bl0, bl1);
                mma_bf16(acc[nt], al0, al1, al2, al3, bh0, bh1);
            }
        }
    }

    float ss0 = 0.0f, ss1 = 0.0f;
    #pragma unroll
    for (int nt = 0; nt < 8; nt++) {
        int c = nt * 8 + (lane & 3) * 2;
        float b0 = __ldg(bias + c), b1 = __ldg(bias + c + 1);
        acc[nt][0] += b0; acc[nt][1] += b1;
        acc[nt][2] += b0; acc[nt][3] += b1;
        ss0 += acc[nt][0] * acc[nt][0] + acc[nt][1] * acc[nt][1];
        ss1 += acc[nt][2] * acc[nt][2] + acc[nt][3] * acc[nt][3];
    }
    ss0 += __shfl_xor_sync(0xffffffffu, ss0, 1);
    ss0 += __shfl_xor_sync(0xffffffffu, ss0, 2);
    ss1 += __shfl_xor_sync(0xffffffffu, ss1, 1);
    ss1 += __shfl_xor_sync(0xffffffffu, ss1, 2);
    float sc0 = INV_SQRT2 / fmaxf(sqrtf(ss0), 1e-12f);
    float sc1 = INV_SQRT2 / fmaxf(sqrtf(ss1), 1e-12f);
    int gr0 = rowbase + r0, gr1 = gr0 + 8;
    #pragma unroll
    for (int nt = 0; nt < 8; nt++) {
        int c = nt * 8 + (lane & 3) * 2;
        if (gr0 < M)
            *(float2*)(outp + (size_t)gr0 * DIM + BR + c) =
                make_float2(acc[nt][0] * sc0, acc[nt][1] * sc0);
        if (gr1 < M)
            *(float2*)(outp + (size_t)gr1 * DIM + BR + c) =
                make_float2(acc[nt][2] * sc1, acc[nt][3] * sc1);
    }
}

// ---------------- scoring: block per batch row ----------------
__global__ void k_score(const int* __restrict__ pos_iids, const int* __restrict__ cand_ids) {
    __shared__ __align__(16) float su[128];
    __shared__ float sc[128];
    int b = blockIdx.x, t = threadIdx.x;
    su[t] = g_batch_u[(size_t)b * DIM + t];
    __syncthreads();
    int pos = pos_iids[b];
    int id = cand_ids[(size_t)b * NCAND + t];
    if (id == pos) id = (id + 1) % N_ITEMS;
    const float4* ip = (const float4*)(g_i_all + (size_t)id * DIM);
    const float4* us = (const float4*)su;
    float a = 0.0f;
    #pragma unroll
    for (int j = 0; j < 32; j++) {
        float4 iv = __ldg(ip + j);
        float4 uv = us[j];
        a += iv.x * uv.x + iv.y * uv.y + iv.z * uv.z + iv.w * uv.w;
    }
    sc[t] = a;
    __syncthreads();

    if (t < 32) {
        const float* pp = g_i_all + (size_t)pos * DIM;
        float p = pp[t] * su[t] + pp[t + 32] * su[t + 32] +
                  pp[t + 64] * su[t + 64] + pp[t + 96] * su[t + 96];
        #pragma unroll
        for (int off = 16; off > 0; off >>= 1) p += __shfl_xor_sync(0xffffffffu, p, off);

        float v0 = sc[t * 4], v1 = sc[t * 4 + 1], v2 = sc[t * 4 + 2], v3 = sc[t * 4 + 3];
        float Lmax = 0.0f, S = 0.0f;
        for (int it = 0; it < NNEG; it++) {
            float best = v0; int bq = 0;
            if (v1 > best) { best = v1; bq = 1; }
            if (v2 > best) { best = v2; bq = 2; }
            if (v3 > best) { best = v3; bq = 3; }
            float wb = best;
            #pragma unroll
            for (int off = 16; off > 0; off >>= 1) wb = fmaxf(wb, __shfl_xor_sync(0xffffffffu, wb, off));
            unsigned m = __ballot_sync(0xffffffffu, best == wb);
            int owner = __ffs(m) - 1;
            if (t == owner) {
                if (bq == 0) v0 = -3.0e38f;
                else if (bq == 1) v1 = -3.0e38f;
                else if (bq == 2) v2 = -3.0e38f;
                else v3 = -3.0e38f;
            }
            float l = wb * 10.0f;
            if (it == 0) { Lmax = l; S = 1.0f; }
            else S += __expf(l - Lmax);
        }
        float lp = p * 10.0f;
        if (lp > Lmax) { S = S * __expf(Lmax - lp) + 1.0f; Lmax = lp; }
        else S += __expf(lp - Lmax);
        float lossb = Lmax + logf(S) - lp;
        if (t == 0) atomicAdd(&g_loss, lossb);
    }
}

__global__ void k_final(float* out) {
    out[0] = g_loss * (1.0f / (float)BATCHB);
}

// ---------------- launch ----------------
extern "C" void kernel_launch(void* const* d_in, const int* in_sizes, int n_in,
                              void* d_out, int out_size) {
    const float* raw_item_embs = (const float*)d_in[0];
    const float* user_sem_base = (const float*)d_in[1];
    const float* sem_w         = (const float*)d_in[2];
    const float* sem_b         = (const float*)d_in[3];
    const float* collab_user_w = (const float*)d_in[4];
    const float* collab_item_w = (const float*)d_in[5];
    const float* adj_vals      = (const float*)d_in[6];
    const int*   adj_rows      = (const int*)d_in[7];
    const int*   adj_cols      = (const int*)d_in[8];
    const int*   uids          = (const int*)d_in[9];
    const int*   pos_iids      = (const int*)d_in[10];
    const int*   cand_ids      = (const int*)d_in[11];
    float* out = (float*)d_out;

    cudaFuncSetAttribute(k_sem_mma<false>, cudaFuncAttributeMaxDynamicSharedMemorySize, SM_BYTES);
    cudaFuncSetAttribute(k_sem_mma<true>,  cudaFuncAttributeMaxDynamicSharedMemorySize, SM_BYTES);

    // side stream: sem GEMMs are independent of the whole GCN chain
    cudaStream_t s2;
    cudaStreamCreateWithFlags(&s2, cudaStreamNonBlocking);
    cudaEvent_t evFork, evJoin;
    cudaEventCreateWithFlags(&evFork, cudaEventDisableTiming);
    cudaEventCreateWithFlags(&evJoin, cudaEventDisableTiming);

    cudaEventRecord(evFork, 0);
    cudaStreamWaitEvent(s2, evFork, 0);
    k_sem_mma<false><<<(N_ITEMS + 127) / 128, 256, SM_BYTES, s2>>>(raw_item_embs, sem_w, sem_b,
                                                                   nullptr, N_ITEMS);
    k_sem_mma<true><<<BATCHB / 128, 256, SM_BYTES, s2>>>(user_sem_base, sem_w, sem_b,
                                                         uids, BATCHB);
    cudaEventRecord(evJoin, s2);

    // main chain
    k_zero<<<(N_TOT + 255) / 256, 256>>>();
    k_mark<<<(BATCHB + 255) / 256, 256>>>(uids);
    k_hist<<<NE / 256, 256>>>(adj_rows);
    k_scan1<<<NB_SCAN, 256>>>();
    k_scan2<<<1, 32>>>();
    k_scan3<<<NB_SCAN, 256>>>();
    k_scatter<<<NE / 256, 256>>>(adj_rows, adj_cols, adj_vals);

    int spmm_blocks = (N_TOT * 32 + 255) / 256;
    k_spmm<0><<<spmm_blocks, 256>>>(collab_user_w, collab_item_w);  // raw -> l1
    k_spmm<1><<<spmm_blocks, 256>>>(collab_user_w, collab_item_w);  // l1 -> l2
    k_spmm<2><<<spmm_blocks, 256>>>(collab_user_w, collab_item_w);  // l2 -> final (masked)

    k_collab_users<<<(BATCHB * 32 + 255) / 256, 256>>>(uids);

    // join: scoring needs both branches
    cudaStreamWaitEvent(0, evJoin, 0);
    k_score<<<BATCHB, 128>>>(pos_iids, cand_ids);
    k_final<<<1, 1>>>(out);

    cudaEventDestroy(evFork);
    cudaEventDestroy(evJoin);
    cudaStreamDestroy(s2);
}